// round 1
// baseline (speedup 1.0000x reference)
#include <cuda_runtime.h>
#include <cuda_bf16.h>
#include <math.h>

#define SQ   2048          // sequence length
#define DM   4096          // d_model
#define PR   2048          // proj
#define NH   32            // heads
#define DH   128           // head dim
#define RP   64            // rope dim

// ---------------- scratch (device globals; no allocation allowed) ----------
__device__ float g_cq   [(size_t)SQ * PR];          // 16 MB
__device__ float g_q    [(size_t)SQ * DM];          // 32 MB
__device__ float g_ckv  [(size_t)SQ * PR];          // 16 MB
__device__ float g_knope[(size_t)SQ * PR];          // 16 MB (S x H*64)
__device__ float g_v    [(size_t)SQ * DM];          // 32 MB
__device__ float g_krope[(size_t)SQ * RP];          // 0.5 MB
__device__ float g_khead[(size_t)SQ * DM];          // 32 MB (S x H*128)
__device__ float g_attno[(size_t)SQ * DM];          // 32 MB
__device__ float g_scores[(size_t)NH * SQ * SQ];    // 512 MB

// ---------------- generic tiled SGEMM -------------------------------------
// C[M,N] = alpha * A[M,K] @ op(B) (+ bias), op(B) = B[K,N] or B[N,K]^T (NT)
// Batched over blockIdx.z with element strides sA/sB/sC.
template <bool NT>
__global__ void __launch_bounds__(256, 2)
sgemm(const float* __restrict__ A, const float* __restrict__ B,
      float* __restrict__ C,
      int M, int N, int K, int lda, int ldb, int ldc,
      long long sA, long long sB, long long sC,
      float alpha, const float* __restrict__ bias)
{
    constexpr int BM = 128, BN = 128, BK = 16;
    __shared__ float As[BK][BM];
    __shared__ float Bs[BK][BN];

    const long long z = blockIdx.z;
    A += z * sA;  B += z * sB;  C += z * sC;

    const int m0 = blockIdx.y * BM;
    const int n0 = blockIdx.x * BN;
    const int tid = threadIdx.x;
    const int tx = tid & 15;          // 0..15  (N direction)
    const int ty = tid >> 4;          // 0..15  (M direction)

    float acc[8][8];
#pragma unroll
    for (int i = 0; i < 8; i++)
#pragma unroll
        for (int j = 0; j < 8; j++) acc[i][j] = 0.0f;

    for (int k0 = 0; k0 < K; k0 += BK) {
        // ---- load A tile (BM x BK), store transposed As[k][m]
        {
            const int r  = tid >> 2;            // 0..63
            const int kq = (tid & 3) * 4;       // 0,4,8,12
#pragma unroll
            for (int rr = 0; rr < 2; rr++) {
                const int row = r + rr * 64;
                const float4 a = *(const float4*)&A[(long long)(m0 + row) * lda + k0 + kq];
                As[kq + 0][row] = a.x;
                As[kq + 1][row] = a.y;
                As[kq + 2][row] = a.z;
                As[kq + 3][row] = a.w;
            }
        }
        // ---- load B tile
        if (!NT) {
            const int r  = tid >> 5;            // 0..7
            const int c4 = (tid & 31) * 4;      // 0..124
#pragma unroll
            for (int rr = 0; rr < 2; rr++) {
                const int row = r + rr * 8;
                float4 b = make_float4(0.f, 0.f, 0.f, 0.f);
                if (n0 + c4 < N)
                    b = *(const float4*)&B[(long long)(k0 + row) * ldb + n0 + c4];
                *(float4*)&Bs[row][c4] = b;
            }
        } else {
            const int r  = tid >> 2;            // 0..63 (n index)
            const int kq = (tid & 3) * 4;
#pragma unroll
            for (int rr = 0; rr < 2; rr++) {
                const int row = r + rr * 64;
                float4 b = make_float4(0.f, 0.f, 0.f, 0.f);
                if (n0 + row < N)
                    b = *(const float4*)&B[(long long)(n0 + row) * ldb + k0 + kq];
                Bs[kq + 0][row] = b.x;
                Bs[kq + 1][row] = b.y;
                Bs[kq + 2][row] = b.z;
                Bs[kq + 3][row] = b.w;
            }
        }
        __syncthreads();

#pragma unroll
        for (int k = 0; k < BK; k++) {
            float ra[8], rb[8];
            *(float4*)&ra[0] = *(const float4*)&As[k][ty * 8];
            *(float4*)&ra[4] = *(const float4*)&As[k][ty * 8 + 4];
            *(float4*)&rb[0] = *(const float4*)&Bs[k][tx * 8];
            *(float4*)&rb[4] = *(const float4*)&Bs[k][tx * 8 + 4];
#pragma unroll
            for (int i = 0; i < 8; i++)
#pragma unroll
                for (int j = 0; j < 8; j++)
                    acc[i][j] += ra[i] * rb[j];
        }
        __syncthreads();
    }

    // ---- epilogue
#pragma unroll
    for (int i = 0; i < 8; i++) {
        const int row = m0 + ty * 8 + i;
#pragma unroll
        for (int j = 0; j < 8; j++) {
            const int col = n0 + tx * 8 + j;
            if (col < N) {
                float v = acc[i][j] * alpha;
                if (bias) v += bias[col];
                C[(long long)row * ldc + col] = v;
            }
        }
    }
}

// ---------------- RoPE ------------------------------------------------------
__device__ __forceinline__ void rope_pair(float* base, int i, int pos)
{
    // freqs over i in [0,32): f = theta^(-2i/128)
    const float f = __expf(-(2.0f * (float)i / 128.0f) * 9.210340371976184f); // ln(10000)
    const float ang = (float)pos * f;
    const float c = cosf(ang), s = sinf(ang);
    const float a = base[i];
    const float b = base[i + 32];
    base[i]      = a * c - b * s;
    base[i + 32] = b * c + a * s;
}

__global__ void rope_q_kernel(float* q, const int* past)
{
    const int idx = blockIdx.x * blockDim.x + threadIdx.x;   // S*H*32
    if (idx >= SQ * NH * 32) return;
    const int s = idx / (NH * 32);
    const int r = idx % (NH * 32);
    const int h = r / 32;
    const int i = r % 32;
    rope_pair(q + (size_t)s * DM + h * DH + 64, i, past[0] + s);
}

__global__ void rope_k_kernel(float* krope, const int* past)
{
    const int idx = blockIdx.x * blockDim.x + threadIdx.x;   // S*32
    if (idx >= SQ * 32) return;
    const int s = idx / 32;
    const int i = idx % 32;
    rope_pair(krope + (size_t)s * RP, i, past[0] + s);
}

// ---------------- assemble K heads: khead[s,h,d] -----------------------------
__global__ void assemble_khead(const float* __restrict__ knope,
                               const float* __restrict__ krope,
                               float* __restrict__ khead)
{
    const int idx = blockIdx.x * blockDim.x + threadIdx.x;   // S*H*128
    if (idx >= SQ * NH * DH) return;
    const int d = idx & (DH - 1);
    const int h = (idx / DH) & (NH - 1);
    const int s = idx / (DH * NH);
    float v;
    if (d < 64) v = knope[(size_t)s * PR + h * 64 + d];
    else        v = krope[(size_t)s * RP + (d - 64)];
    khead[idx] = v;
}

// ---------------- row softmax ------------------------------------------------
__global__ void softmax_rows(float* __restrict__ scores)
{
    const int row = blockIdx.x;
    const int h   = blockIdx.y;
    float* p = scores + ((size_t)h * SQ + row) * SQ;
    __shared__ float red[256];
    const int tid = threadIdx.x;

    float m = -1e30f;
    for (int i = tid; i < SQ; i += 256) m = fmaxf(m, p[i]);
    red[tid] = m; __syncthreads();
    for (int s = 128; s > 0; s >>= 1) {
        if (tid < s) red[tid] = fmaxf(red[tid], red[tid + s]);
        __syncthreads();
    }
    m = red[0]; __syncthreads();

    float sum = 0.0f;
    for (int i = tid; i < SQ; i += 256) {
        const float e = expf(p[i] - m);
        p[i] = e;
        sum += e;
    }
    red[tid] = sum; __syncthreads();
    for (int s = 128; s > 0; s >>= 1) {
        if (tid < s) red[tid] += red[tid + s];
        __syncthreads();
    }
    const float inv = 1.0f / red[0];
    for (int i = tid; i < SQ; i += 256) p[i] *= inv;
}

// ---------------- launch ------------------------------------------------------
static inline dim3 gemm_grid(int M, int N, int Z)
{
    return dim3((N + 127) / 128, (M + 127) / 128, Z);
}

extern "C" void kernel_launch(void* const* d_in, const int* in_sizes, int n_in,
                              void* d_out, int out_size)
{
    const float* x        = (const float*)d_in[0];
    const float* W_DQ     = (const float*)d_in[1];
    const float* W_UQ     = (const float*)d_in[2];
    const float* W_DKV    = (const float*)d_in[3];
    const float* W_UK     = (const float*)d_in[4];
    const float* W_UV     = (const float*)d_in[5];
    const float* W_K_rope = (const float*)d_in[6];
    const float* W_O      = (const float*)d_in[7];
    const float* b_O      = (const float*)d_in[8];
    const int*   past     = (const int*)d_in[9];
    float* out = (float*)d_out;

    float *cq, *q, *ckv, *knope, *v, *krope, *khead, *attno, *scores;
    cudaGetSymbolAddress((void**)&cq,     g_cq);
    cudaGetSymbolAddress((void**)&q,      g_q);
    cudaGetSymbolAddress((void**)&ckv,    g_ckv);
    cudaGetSymbolAddress((void**)&knope,  g_knope);
    cudaGetSymbolAddress((void**)&v,      g_v);
    cudaGetSymbolAddress((void**)&krope,  g_krope);
    cudaGetSymbolAddress((void**)&khead,  g_khead);
    cudaGetSymbolAddress((void**)&attno,  g_attno);
    cudaGetSymbolAddress((void**)&scores, g_scores);

    const dim3 blk(256);

    // 1. cq = x @ W_DQ                       (2048 x 2048 x 4096)
    sgemm<false><<<gemm_grid(SQ, PR, 1), blk>>>(x, W_DQ, cq,
        SQ, PR, DM, DM, PR, PR, 0, 0, 0, 1.0f, nullptr);
    // 2. q = cq @ W_UQ                       (2048 x 4096 x 2048)
    sgemm<false><<<gemm_grid(SQ, DM, 1), blk>>>(cq, W_UQ, q,
        SQ, DM, PR, PR, DM, DM, 0, 0, 0, 1.0f, nullptr);
    // 3. ckv = x @ W_DKV
    sgemm<false><<<gemm_grid(SQ, PR, 1), blk>>>(x, W_DKV, ckv,
        SQ, PR, DM, DM, PR, PR, 0, 0, 0, 1.0f, nullptr);
    // 4. knope = ckv @ W_UK                  (2048 x 2048 x 2048)
    sgemm<false><<<gemm_grid(SQ, PR, 1), blk>>>(ckv, W_UK, knope,
        SQ, PR, PR, PR, PR, PR, 0, 0, 0, 1.0f, nullptr);
    // 5. v = ckv @ W_UV                      (2048 x 4096 x 2048)
    sgemm<false><<<gemm_grid(SQ, DM, 1), blk>>>(ckv, W_UV, v,
        SQ, DM, PR, PR, DM, DM, 0, 0, 0, 1.0f, nullptr);
    // 6. krope = x @ W_K_rope                (2048 x 64 x 4096)
    sgemm<false><<<gemm_grid(SQ, RP, 1), blk>>>(x, W_K_rope, krope,
        SQ, RP, DM, DM, RP, RP, 0, 0, 0, 1.0f, nullptr);

    // 7. RoPE (in place)
    rope_q_kernel<<<(SQ * NH * 32 + 255) / 256, blk>>>(q, past);
    rope_k_kernel<<<(SQ * 32 + 255) / 256, blk>>>(krope, past);

    // 8. assemble k_head[s, h, 0:64]=knope, [64:128]=krope
    assemble_khead<<<(SQ * NH * DH + 255) / 256, blk>>>(knope, krope, khead);

    // 9. scores[h] = (Q_h @ K_h^T) / sqrt(128), batched over 32 heads
    const float alpha = 0.08838834764831845f;   // 1/sqrt(128)
    sgemm<true><<<gemm_grid(SQ, SQ, NH), blk>>>(q, khead, scores,
        SQ, SQ, DH, DM, DM, SQ,
        (long long)DH, (long long)DH, (long long)SQ * SQ, alpha, nullptr);

    // 10. softmax over rows
    softmax_rows<<<dim3(SQ, NH), blk>>>(scores);

    // 11. attno[h] = P_h @ V_h               (2048 x 128 x 2048) batched
    sgemm<false><<<gemm_grid(SQ, DH, NH), blk>>>(scores, v, attno,
        SQ, DH, SQ, SQ, DM, DM,
        (long long)SQ * SQ, (long long)DH, (long long)DH, 1.0f, nullptr);

    // 12. out = attno @ W_O + b_O            (2048 x 4096 x 4096)
    sgemm<false><<<gemm_grid(SQ, DM, 1), blk>>>(attno, W_O, out,
        SQ, DM, DM, DM, DM, DM, 0, 0, 0, 1.0f, b_O);
}

// round 3
// speedup vs baseline: 2.2938x; 2.2938x over previous
#include <cuda_runtime.h>
#include <cuda_bf16.h>
#include <cstdint>
#include <math.h>

#define SQ   2048
#define DM   4096
#define PR   2048
#define NH   32
#define DH   128
#define RP   64

// ===================== small helpers ========================================
static __device__ __forceinline__ uint32_t smem_u32(const void* p) {
    uint32_t a;
    asm("{ .reg .u64 t; cvta.to.shared.u64 t, %1; cvt.u32.u64 %0, t; }"
        : "=r"(a) : "l"(p));
    return a;
}

// pack two floats -> bf16x2 (lo half = a, hi half = b)
static __device__ __forceinline__ uint32_t cvt_bf16x2(float a, float b) {
    uint32_t r;
    asm("cvt.rn.bf16x2.f32 %0, %1, %2;" : "=r"(r) : "f"(b), "f"(a));
    return r;
}

#define LDSM4(r, addr) \
    asm volatile("ldmatrix.sync.aligned.m8n8.x4.shared.b16 {%0,%1,%2,%3}, [%4];" \
        : "=r"((r)[0]), "=r"((r)[1]), "=r"((r)[2]), "=r"((r)[3]) : "r"(addr))

#define MMA(d, a, b0v, b1v) \
    asm volatile("mma.sync.aligned.m16n8k16.row.col.f32.bf16.bf16.f32 " \
        "{%0,%1,%2,%3}, {%4,%5,%6,%7}, {%8,%9}, {%0,%1,%2,%3};" \
        : "+f"((d)[0]), "+f"((d)[1]), "+f"((d)[2]), "+f"((d)[3]) \
        : "r"((a)[0]), "r"((a)[1]), "r"((a)[2]), "r"((a)[3]), "r"(b0v), "r"(b1v))

#define CP_ASYNC16(sp, gp) \
    asm volatile("cp.async.cg.shared.global [%0], [%1], 16;" :: "r"(sp), "l"(gp))
#define CP_COMMIT() asm volatile("cp.async.commit_group;" ::: "memory")
#define CP_WAIT2()  asm volatile("cp.async.wait_group 2;" ::: "memory")

// ===================== scratch (device globals) =============================
__device__ float g_q    [(size_t)SQ * DM];
__device__ float g_knope[(size_t)SQ * PR];
__device__ float g_v    [(size_t)SQ * DM];
__device__ float g_krope[(size_t)SQ * RP];
__device__ float g_scores[(size_t)NH * SQ * SQ];          // 512 MB

// split activations (A operands, row-major [M,K])
__device__ __nv_bfloat16 g_xa_hi [(size_t)SQ * DM],  g_xa_lo [(size_t)SQ * DM];
__device__ __nv_bfloat16 g_cq_hi [(size_t)SQ * PR],  g_cq_lo [(size_t)SQ * PR];
__device__ __nv_bfloat16 g_ckv_hi[(size_t)SQ * PR],  g_ckv_lo[(size_t)SQ * PR];
__device__ __nv_bfloat16 g_qa_hi [(size_t)SQ * DM],  g_qa_lo [(size_t)SQ * DM];
__device__ __nv_bfloat16 g_ao_hi [(size_t)SQ * DM],  g_ao_lo [(size_t)SQ * DM];
__device__ __nv_bfloat16 g_p_hi  [(size_t)NH * SQ * SQ],  g_p_lo [(size_t)NH * SQ * SQ]; // 512 MB

// split, transposed B operands ([N,K] K-major)
__device__ __nv_bfloat16 g_wdq_hi [(size_t)PR * DM],  g_wdq_lo [(size_t)PR * DM];
__device__ __nv_bfloat16 g_wuq_hi [(size_t)DM * PR],  g_wuq_lo [(size_t)DM * PR];
__device__ __nv_bfloat16 g_wdkv_hi[(size_t)PR * DM],  g_wdkv_lo[(size_t)PR * DM];
__device__ __nv_bfloat16 g_wuk_hi [(size_t)PR * PR],  g_wuk_lo [(size_t)PR * PR];
__device__ __nv_bfloat16 g_wuv_hi [(size_t)DM * PR],  g_wuv_lo [(size_t)DM * PR];
__device__ __nv_bfloat16 g_wkr_hi [(size_t)RP * DM],  g_wkr_lo [(size_t)RP * DM];
__device__ __nv_bfloat16 g_wo_hi  [(size_t)DM * DM],  g_wo_lo  [(size_t)DM * DM];
__device__ __nv_bfloat16 g_kh_hi  [(size_t)NH * SQ * DH], g_kh_lo [(size_t)NH * SQ * DH];
__device__ __nv_bfloat16 g_vt_hi  [(size_t)NH * DH * SQ], g_vt_lo [(size_t)NH * DH * SQ];

// ===================== split-bf16 HMMA GEMM =================================
// C = alpha * A @ B^T (+bias).  A: split bf16 hi/lo [M,K] row-major.
// B: split bf16 hi/lo [N,K] K-major.  3-term: AhBh + AhBl + AlBh.
// CTA tile 128x128, BK=32, 8 warps (2x4), warp tile 64x32, 3-stage cp.async.
// Output: fp32 (Cf) and/or split bf16 (Chi/Clo).
#define STAGE_BYTES 40960              // 4 matrices * 128 rows * 80 B
#define GEMM_SMEM   (3 * STAGE_BYTES)  // 122880

__global__ void __launch_bounds__(256, 1)
gemm_bf16(const __nv_bfloat16* __restrict__ Ahi, const __nv_bfloat16* __restrict__ Alo,
          const __nv_bfloat16* __restrict__ Bhi, const __nv_bfloat16* __restrict__ Blo,
          float* __restrict__ Cf,
          __nv_bfloat16* __restrict__ Chi, __nv_bfloat16* __restrict__ Clo,
          int M, int N, int K, int lda, int ldb, int ldc,
          long long sA, long long sB, long long sC,
          float alpha, const float* __restrict__ bias)
{
    extern __shared__ char smem[];
    const uint32_t sbase = smem_u32(smem);
    const int tid  = threadIdx.x;
    const int lane = tid & 31;
    const int w    = tid >> 5;
    const int wm   = w & 1;        // M dir (2)
    const int wn   = w >> 1;       // N dir (4)

    const long long z = blockIdx.z;
    Ahi += z * sA;  Alo += z * sA;
    Bhi += z * sB;  Blo += z * sB;
    if (Cf)  Cf  += z * sC;
    if (Chi) { Chi += z * sC; Clo += z * sC; }

    const int m0 = blockIdx.y * 128;
    const int n0 = blockIdx.x * 128;
    const int nk = K >> 5;

    // per-thread load mapping: 8 chunks of 16B per stage
    const int lr   = tid >> 2;        // 0..63
    const int lcol = tid & 3;         // 0..3

    auto load_stage = [&](int kt, int slot) {
        const int k0 = kt << 5;
        const uint32_t sb = sbase + slot * STAGE_BYTES;
#pragma unroll
        for (int i = 0; i < 8; ++i) {
            const int r   = ((i & 1) << 6) + lr;     // 0..127
            const int mat = i >> 1;                  // 0:Ah 1:Al 2:Bh 3:Bl
            const __nv_bfloat16* gp;
            if (mat < 2) {
                const __nv_bfloat16* base = (mat == 0) ? Ahi : Alo;
                gp = base + (long long)(m0 + r) * lda + k0 + lcol * 8;
            } else {
                int rn = n0 + r; if (rn >= N) rn = N - 1;
                const __nv_bfloat16* base = (mat == 2) ? Bhi : Blo;
                gp = base + (long long)rn * ldb + k0 + lcol * 8;
            }
            const uint32_t sp = sb + mat * 10240 + r * 80 + lcol * 16;
            CP_ASYNC16(sp, gp);
        }
        CP_COMMIT();
    };

    // ldmatrix per-lane byte offsets (padded 80B rows)
    const uint32_t aOff = (uint32_t)((wm * 64 + (lane & 15)) * 80 + ((lane >> 4) & 1) * 16);
    const uint32_t bOff = (uint32_t)((wn * 32 + ((lane >> 4) & 1) * 8 + (lane & 7)) * 80
                                     + ((lane >> 3) & 1) * 16);

    float acc[4][4][4];
#pragma unroll
    for (int a = 0; a < 4; a++)
#pragma unroll
        for (int b = 0; b < 4; b++)
#pragma unroll
            for (int c = 0; c < 4; c++) acc[a][b][c] = 0.0f;

    load_stage(0, 0);
    if (nk > 1) load_stage(1, 1); else CP_COMMIT();

    for (int kt = 0; kt < nk; ++kt) {
        if (kt + 2 < nk) load_stage(kt + 2, (kt + 2) % 3);
        else CP_COMMIT();
        CP_WAIT2();
        __syncthreads();

        const uint32_t sb = sbase + (kt % 3) * STAGE_BYTES;
#pragma unroll
        for (int kk = 0; kk < 2; ++kk) {
            uint32_t ah[4][4], al[4][4], bh[2][4], bl[2][4];
#pragma unroll
            for (int mt = 0; mt < 4; ++mt) {
                const uint32_t ad = sb + aOff + mt * 1280 + kk * 32;
                LDSM4(ah[mt], ad);
                LDSM4(al[mt], ad + 10240);
            }
#pragma unroll
            for (int bt = 0; bt < 2; ++bt) {
                const uint32_t bd = sb + 20480 + bOff + bt * 1280 + kk * 32;
                LDSM4(bh[bt], bd);
                LDSM4(bl[bt], bd + 10240);
            }
#pragma unroll
            for (int mt = 0; mt < 4; ++mt)
#pragma unroll
                for (int nt = 0; nt < 4; ++nt) {
                    const int bt = nt >> 1, s2 = (nt & 1) * 2;
                    MMA(acc[mt][nt], ah[mt], bh[bt][s2], bh[bt][s2 + 1]);
                    MMA(acc[mt][nt], ah[mt], bl[bt][s2], bl[bt][s2 + 1]);
                    MMA(acc[mt][nt], al[mt], bh[bt][s2], bh[bt][s2 + 1]);
                }
        }
        __syncthreads();
    }

    // ---- epilogue ----
    const int er = lane >> 2;
    const int ec = (lane & 3) << 1;
#pragma unroll
    for (int mt = 0; mt < 4; ++mt) {
#pragma unroll
        for (int nt = 0; nt < 4; ++nt) {
            const int gr = m0 + wm * 64 + mt * 16 + er;
            const int gc = n0 + wn * 32 + nt * 8 + ec;
            if (gc >= N) continue;
            float v0 = acc[mt][nt][0] * alpha;
            float v1 = acc[mt][nt][1] * alpha;
            float v2 = acc[mt][nt][2] * alpha;
            float v3 = acc[mt][nt][3] * alpha;
            if (bias) {
                const float b0 = bias[gc], b1 = bias[gc + 1];
                v0 += b0; v1 += b1; v2 += b0; v3 += b1;
            }
            const long long o0 = (long long)gr * ldc + gc;
            const long long o1 = (long long)(gr + 8) * ldc + gc;
            if (Cf) {
                *(float2*)&Cf[o0] = make_float2(v0, v1);
                *(float2*)&Cf[o1] = make_float2(v2, v3);
            }
            if (Chi) {
                uint32_t h = cvt_bf16x2(v0, v1);
                uint32_t l = cvt_bf16x2(v0 - __uint_as_float(h << 16),
                                        v1 - __uint_as_float(h & 0xFFFF0000u));
                *(uint32_t*)&Chi[o0] = h;
                *(uint32_t*)&Clo[o0] = l;
                h = cvt_bf16x2(v2, v3);
                l = cvt_bf16x2(v2 - __uint_as_float(h << 16),
                               v3 - __uint_as_float(h & 0xFFFF0000u));
                *(uint32_t*)&Chi[o1] = h;
                *(uint32_t*)&Clo[o1] = l;
            }
        }
    }
}

// ===================== elementwise split fp32 -> bf16 hi/lo ==================
__global__ void split_f32(const float4* __restrict__ in,
                          uint2* __restrict__ hi, uint2* __restrict__ lo, int n4)
{
    const int i = blockIdx.x * blockDim.x + threadIdx.x;
    if (i >= n4) return;
    const float4 f = in[i];
    const uint32_t h01 = cvt_bf16x2(f.x, f.y);
    const uint32_t h23 = cvt_bf16x2(f.z, f.w);
    const uint32_t l01 = cvt_bf16x2(f.x - __uint_as_float(h01 << 16),
                                    f.y - __uint_as_float(h01 & 0xFFFF0000u));
    const uint32_t l23 = cvt_bf16x2(f.z - __uint_as_float(h23 << 16),
                                    f.w - __uint_as_float(h23 & 0xFFFF0000u));
    hi[i] = make_uint2(h01, h23);
    lo[i] = make_uint2(l01, l23);
}

// ===================== transpose + split fp32 -> bf16 hi/lo =================
__global__ void transpose_split(const float* __restrict__ in,
                                __nv_bfloat16* __restrict__ ohi,
                                __nv_bfloat16* __restrict__ olo,
                                int R, int C, int ldin, int ldout,
                                long long sIn, long long sOut)
{
    __shared__ float t[32][33];
    const long long z = blockIdx.z;
    in += z * sIn;  ohi += z * sOut;  olo += z * sOut;
    const int c0 = blockIdx.x * 32, r0 = blockIdx.y * 32;
    const int tx = threadIdx.x, ty = threadIdx.y;
#pragma unroll
    for (int j = 0; j < 32; j += 8)
        t[ty + j][tx] = in[(long long)(r0 + ty + j) * ldin + c0 + tx];
    __syncthreads();
#pragma unroll
    for (int j = 0; j < 32; j += 8) {
        const float f = t[tx][ty + j];
        const __nv_bfloat16 h = __float2bfloat16(f);
        const __nv_bfloat16 l = __float2bfloat16(f - __bfloat162float(h));
        const long long o = (long long)(c0 + ty + j) * ldout + r0 + tx;
        ohi[o] = h;  olo[o] = l;
    }
}

// ===================== RoPE ==================================================
__device__ __forceinline__ void rope_pair(float* base, int i, int pos)
{
    const float f = __expf(-(2.0f * (float)i / 128.0f) * 9.210340371976184f);
    const float ang = (float)pos * f;
    const float c = cosf(ang), s = sinf(ang);
    const float a = base[i];
    const float b = base[i + 32];
    base[i]      = a * c - b * s;
    base[i + 32] = b * c + a * s;
}

__global__ void rope_q_kernel(float* q, const int* past)
{
    const int idx = blockIdx.x * blockDim.x + threadIdx.x;
    if (idx >= SQ * NH * 32) return;
    const int s = idx / (NH * 32);
    const int r = idx % (NH * 32);
    rope_pair(q + (size_t)s * DM + (r / 32) * DH + 64, r % 32, past[0] + s);
}

__global__ void rope_k_kernel(float* krope, const int* past)
{
    const int idx = blockIdx.x * blockDim.x + threadIdx.x;
    if (idx >= SQ * 32) return;
    rope_pair(krope + (size_t)(idx / 32) * RP, idx % 32, past[0] + idx / 32);
}

// ===================== assemble K heads -> bf16 hi/lo [h][s][d] ==============
__global__ void assemble_khead_split(const float* __restrict__ knope,
                                     const float* __restrict__ krope,
                                     __nv_bfloat16* __restrict__ khi,
                                     __nv_bfloat16* __restrict__ klo)
{
    const int idx = blockIdx.x * blockDim.x + threadIdx.x;
    if (idx >= NH * SQ * DH) return;
    const int d = idx & (DH - 1);
    const int s = (idx >> 7) & (SQ - 1);
    const int h = idx >> 18;
    float v;
    if (d < 64) v = knope[(size_t)s * PR + h * 64 + d];
    else        v = krope[(size_t)s * RP + (d - 64)];
    const __nv_bfloat16 hb = __float2bfloat16(v);
    khi[idx] = hb;
    klo[idx] = __float2bfloat16(v - __bfloat162float(hb));
}

// ===================== softmax -> split bf16 probs ===========================
__global__ void softmax_split(const float* __restrict__ scores,
                              __nv_bfloat16* __restrict__ phi,
                              __nv_bfloat16* __restrict__ plo)
{
    const int row = blockIdx.x;
    const int h   = blockIdx.y;
    const size_t base = ((size_t)h * SQ + row) * SQ;
    const float* p = scores + base;
    __nv_bfloat16* oh = phi + base;
    __nv_bfloat16* ol = plo + base;
    const int tid = threadIdx.x;
    __shared__ float red[256];

    float vals[8];
    float m = -1e30f;
#pragma unroll
    for (int i = 0; i < 8; ++i) {
        vals[i] = p[tid + i * 256];
        m = fmaxf(m, vals[i]);
    }
    red[tid] = m; __syncthreads();
    for (int s = 128; s > 0; s >>= 1) {
        if (tid < s) red[tid] = fmaxf(red[tid], red[tid + s]);
        __syncthreads();
    }
    m = red[0]; __syncthreads();

    float sum = 0.0f;
#pragma unroll
    for (int i = 0; i < 8; ++i) {
        vals[i] = __expf(vals[i] - m);
        sum += vals[i];
    }
    red[tid] = sum; __syncthreads();
    for (int s = 128; s > 0; s >>= 1) {
        if (tid < s) red[tid] += red[tid + s];
        __syncthreads();
    }
    const float inv = 1.0f / red[0];
#pragma unroll
    for (int i = 0; i < 8; ++i) {
        const float v = vals[i] * inv;
        const __nv_bfloat16 hb = __float2bfloat16(v);
        oh[tid + i * 256] = hb;
        ol[tid + i * 256] = __float2bfloat16(v - __bfloat162float(hb));
    }
}

// ===================== launch ================================================
extern "C" void kernel_launch(void* const* d_in, const int* in_sizes, int n_in,
                              void* d_out, int out_size)
{
    const float* x        = (const float*)d_in[0];
    const float* W_DQ     = (const float*)d_in[1];
    const float* W_UQ     = (const float*)d_in[2];
    const float* W_DKV    = (const float*)d_in[3];
    const float* W_UK     = (const float*)d_in[4];
    const float* W_UV     = (const float*)d_in[5];
    const float* W_K_rope = (const float*)d_in[6];
    const float* W_O      = (const float*)d_in[7];
    const float* b_O      = (const float*)d_in[8];
    const int*   past     = (const int*)d_in[9];
    float* out = (float*)d_out;

    float *q, *knope, *v, *krope, *scores;
    cudaGetSymbolAddress((void**)&q,      g_q);
    cudaGetSymbolAddress((void**)&knope,  g_knope);
    cudaGetSymbolAddress((void**)&v,      g_v);
    cudaGetSymbolAddress((void**)&krope,  g_krope);
    cudaGetSymbolAddress((void**)&scores, g_scores);

    __nv_bfloat16 *xa_h, *xa_l, *cq_h, *cq_l, *ckv_h, *ckv_l, *qa_h, *qa_l,
                  *ao_h, *ao_l, *p_h, *p_l,
                  *wdq_h, *wdq_l, *wuq_h, *wuq_l, *wdkv_h, *wdkv_l,
                  *wuk_h, *wuk_l, *wuv_h, *wuv_l, *wkr_h, *wkr_l,
                  *wo_h, *wo_l, *kh_h, *kh_l, *vt_h, *vt_l;
    cudaGetSymbolAddress((void**)&xa_h,  g_xa_hi);  cudaGetSymbolAddress((void**)&xa_l,  g_xa_lo);
    cudaGetSymbolAddress((void**)&cq_h,  g_cq_hi);  cudaGetSymbolAddress((void**)&cq_l,  g_cq_lo);
    cudaGetSymbolAddress((void**)&ckv_h, g_ckv_hi); cudaGetSymbolAddress((void**)&ckv_l, g_ckv_lo);
    cudaGetSymbolAddress((void**)&qa_h,  g_qa_hi);  cudaGetSymbolAddress((void**)&qa_l,  g_qa_lo);
    cudaGetSymbolAddress((void**)&ao_h,  g_ao_hi);  cudaGetSymbolAddress((void**)&ao_l,  g_ao_lo);
    cudaGetSymbolAddress((void**)&p_h,   g_p_hi);   cudaGetSymbolAddress((void**)&p_l,   g_p_lo);
    cudaGetSymbolAddress((void**)&wdq_h,  g_wdq_hi);  cudaGetSymbolAddress((void**)&wdq_l,  g_wdq_lo);
    cudaGetSymbolAddress((void**)&wuq_h,  g_wuq_hi);  cudaGetSymbolAddress((void**)&wuq_l,  g_wuq_lo);
    cudaGetSymbolAddress((void**)&wdkv_h, g_wdkv_hi); cudaGetSymbolAddress((void**)&wdkv_l, g_wdkv_lo);
    cudaGetSymbolAddress((void**)&wuk_h,  g_wuk_hi);  cudaGetSymbolAddress((void**)&wuk_l,  g_wuk_lo);
    cudaGetSymbolAddress((void**)&wuv_h,  g_wuv_hi);  cudaGetSymbolAddress((void**)&wuv_l,  g_wuv_lo);
    cudaGetSymbolAddress((void**)&wkr_h,  g_wkr_hi);  cudaGetSymbolAddress((void**)&wkr_l,  g_wkr_lo);
    cudaGetSymbolAddress((void**)&wo_h,   g_wo_hi);   cudaGetSymbolAddress((void**)&wo_l,   g_wo_lo);
    cudaGetSymbolAddress((void**)&kh_h,   g_kh_hi);   cudaGetSymbolAddress((void**)&kh_l,   g_kh_lo);
    cudaGetSymbolAddress((void**)&vt_h,   g_vt_hi);   cudaGetSymbolAddress((void**)&vt_l,   g_vt_lo);

    cudaFuncSetAttribute(gemm_bf16, cudaFuncAttributeMaxDynamicSharedMemorySize, GEMM_SMEM);

    const dim3 blk(256);
    const dim3 tb(32, 8);

    // ---- weight transpose+split: [K,N] fp32 -> [N,K] bf16 hi/lo ----
    transpose_split<<<dim3(PR / 32, DM / 32, 1), tb>>>(W_DQ,  wdq_h,  wdq_l,  DM, PR, PR, DM, 0, 0);
    transpose_split<<<dim3(DM / 32, PR / 32, 1), tb>>>(W_UQ,  wuq_h,  wuq_l,  PR, DM, DM, PR, 0, 0);
    transpose_split<<<dim3(PR / 32, DM / 32, 1), tb>>>(W_DKV, wdkv_h, wdkv_l, DM, PR, PR, DM, 0, 0);
    transpose_split<<<dim3(PR / 32, PR / 32, 1), tb>>>(W_UK,  wuk_h,  wuk_l,  PR, PR, PR, PR, 0, 0);
    transpose_split<<<dim3(DM / 32, PR / 32, 1), tb>>>(W_UV,  wuv_h,  wuv_l,  PR, DM, DM, PR, 0, 0);
    transpose_split<<<dim3(RP / 32, DM / 32, 1), tb>>>(W_K_rope, wkr_h, wkr_l, DM, RP, RP, DM, 0, 0);
    transpose_split<<<dim3(DM / 32, DM / 32, 1), tb>>>(W_O,   wo_h,   wo_l,   DM, DM, DM, DM, 0, 0);

    // ---- split x ----
    split_f32<<<(SQ * DM / 4 + 255) / 256, blk>>>(
        (const float4*)x, (uint2*)xa_h, (uint2*)xa_l, SQ * DM / 4);

    // 1. cq = x @ W_DQ  (split output only)
    gemm_bf16<<<dim3(PR / 128, SQ / 128, 1), blk, GEMM_SMEM>>>(
        xa_h, xa_l, wdq_h, wdq_l, nullptr, cq_h, cq_l,
        SQ, PR, DM, DM, DM, PR, 0, 0, 0, 1.0f, nullptr);
    // 3. ckv = x @ W_DKV (split output only)
    gemm_bf16<<<dim3(PR / 128, SQ / 128, 1), blk, GEMM_SMEM>>>(
        xa_h, xa_l, wdkv_h, wdkv_l, nullptr, ckv_h, ckv_l,
        SQ, PR, DM, DM, DM, PR, 0, 0, 0, 1.0f, nullptr);
    // 6. krope = x @ W_K_rope (fp32, N=64)
    gemm_bf16<<<dim3(1, SQ / 128, 1), blk, GEMM_SMEM>>>(
        xa_h, xa_l, wkr_h, wkr_l, krope, nullptr, nullptr,
        SQ, RP, DM, DM, DM, RP, 0, 0, 0, 1.0f, nullptr);
    // 2. q = cq @ W_UQ (fp32 — rope needs it)
    gemm_bf16<<<dim3(DM / 128, SQ / 128, 1), blk, GEMM_SMEM>>>(
        cq_h, cq_l, wuq_h, wuq_l, q, nullptr, nullptr,
        SQ, DM, PR, PR, PR, DM, 0, 0, 0, 1.0f, nullptr);
    // 4. knope = ckv @ W_UK (fp32)
    gemm_bf16<<<dim3(PR / 128, SQ / 128, 1), blk, GEMM_SMEM>>>(
        ckv_h, ckv_l, wuk_h, wuk_l, knope, nullptr, nullptr,
        SQ, PR, PR, PR, PR, PR, 0, 0, 0, 1.0f, nullptr);
    // 5. v = ckv @ W_UV (fp32)
    gemm_bf16<<<dim3(DM / 128, SQ / 128, 1), blk, GEMM_SMEM>>>(
        ckv_h, ckv_l, wuv_h, wuv_l, v, nullptr, nullptr,
        SQ, DM, PR, PR, PR, DM, 0, 0, 0, 1.0f, nullptr);

    // 7. RoPE in place + split q
    rope_q_kernel<<<(SQ * NH * 32 + 255) / 256, blk>>>(q, past);
    rope_k_kernel<<<(SQ * 32 + 255) / 256, blk>>>(krope, past);
    split_f32<<<(SQ * DM / 4 + 255) / 256, blk>>>(
        (const float4*)q, (uint2*)qa_h, (uint2*)qa_l, SQ * DM / 4);

    // 8. K heads -> split [h][s][d];  V^T per head -> split [h][d][s]
    assemble_khead_split<<<(NH * SQ * DH + 255) / 256, blk>>>(knope, krope, kh_h, kh_l);
    transpose_split<<<dim3(DH / 32, SQ / 32, NH), tb>>>(
        v, vt_h, vt_l, SQ, DH, DM, SQ, (long long)DH, (long long)DH * SQ);

    // 9. scores[h] = (Q_h @ K_h^T) / sqrt(128)  (fp32)
    const float alpha = 0.08838834764831845f;
    gemm_bf16<<<dim3(SQ / 128, SQ / 128, NH), blk, GEMM_SMEM>>>(
        qa_h, qa_l, kh_h, kh_l, scores, nullptr, nullptr,
        SQ, SQ, DH, DM, DH, SQ,
        (long long)DH, (long long)SQ * DH, (long long)SQ * SQ, alpha, nullptr);

    // 10. softmax -> split probs
    softmax_split<<<dim3(SQ, NH), blk>>>(scores, p_h, p_l);

    // 11. attno[h] = P_h @ V_h (split output, interleaved [s][h*DH])
    gemm_bf16<<<dim3(1, SQ / 128, NH), blk, GEMM_SMEM>>>(
        p_h, p_l, vt_h, vt_l, nullptr, ao_h, ao_l,
        SQ, DH, SQ, SQ, SQ, DM,
        (long long)SQ * SQ, (long long)DH * SQ, (long long)DH, 1.0f, nullptr);

    // 12. out = attno @ W_O + b_O (fp32)
    gemm_bf16<<<dim3(DM / 128, SQ / 128, 1), blk, GEMM_SMEM>>>(
        ao_h, ao_l, wo_h, wo_l, out, nullptr, nullptr,
        SQ, DM, DM, DM, DM, DM, 0, 0, 0, 1.0f, b_O);
}